// round 12
// baseline (speedup 1.0000x reference)
#include <cuda_runtime.h>
#include <cstdint>

#define MAX_E 100000
#define MAX_T 1000000
#define CCH   64
#define SCAN_BLK 512
#define MAX_SCAN_BLOCKS ((MAX_E + SCAN_BLK - 1) / SCAN_BLK)
#define TPB1  128   // pass1: CSR slots per block
#define RS    65    // padded smem row stride (odd => conflict-free)

// Scratch (device globals — zero at module load; g_cnt/g_cursor re-zeroed by
// k_edge at the end of every run => zero on entry for every replay).
__device__ float4   g_rnorm4[MAX_E];
__device__ unsigned g_cnt[MAX_E];
__device__ unsigned g_off[MAX_E];    // block-local exclusive prefix (scan1)
__device__ unsigned g_cursor[MAX_E];
__device__ unsigned g_bsum[MAX_SCAN_BLOCKS];  // exclusive block offsets (scan2)
__device__ int4     g_pack[MAX_T];   // {src, dst, cos_theta bits, 0}, CSR-ordered
__device__ int2     g_se[MAX_T];     // {src, exp(logit) bits}, CSR-ordered

// ---------------------------------------------------------------------------
__global__ void k_prep_count(const float* __restrict__ r,
                             const int* __restrict__ tdst, int E, int T) {
    int i = blockIdx.x * blockDim.x + threadIdx.x;
    if (i < E) {
        float x = r[3 * i + 0], y = r[3 * i + 1], z = r[3 * i + 2];
        float inv = rsqrtf(x * x + y * y + z * z);
        g_rnorm4[i] = make_float4(x * inv, y * inv, z * inv, 0.0f);
    }
    if (i < T) atomicAdd(&g_cnt[tdst[i]], 1u);
}

// -------- 2-kernel scan; final block-offset add folded into consumers -------
__global__ void k_scan1(int E) {
    __shared__ unsigned sh[SCAN_BLK];
    int i = blockIdx.x * SCAN_BLK + threadIdx.x;
    unsigned v = (i < E) ? g_cnt[i] : 0u;
    sh[threadIdx.x] = v;
    __syncthreads();
    unsigned incl = v;
    for (int ofs = 1; ofs < SCAN_BLK; ofs <<= 1) {
        unsigned add = (threadIdx.x >= ofs) ? sh[threadIdx.x - ofs] : 0u;
        __syncthreads();
        incl += add;
        sh[threadIdx.x] = incl;
        __syncthreads();
    }
    if (i < E) g_off[i] = incl - v;          // block-local exclusive
    if (threadIdx.x == SCAN_BLK - 1) g_bsum[blockIdx.x] = incl;
}

__global__ void k_scan2(int nb) {
    __shared__ unsigned sh[SCAN_BLK];
    unsigned v = (threadIdx.x < nb) ? g_bsum[threadIdx.x] : 0u;
    sh[threadIdx.x] = v;
    __syncthreads();
    unsigned incl = v;
    for (int ofs = 1; ofs < SCAN_BLK; ofs <<= 1) {
        unsigned add = (threadIdx.x >= ofs) ? sh[threadIdx.x - ofs] : 0u;
        __syncthreads();
        incl += add;
        sh[threadIdx.x] = incl;
        __syncthreads();
    }
    if (threadIdx.x < nb) g_bsum[threadIdx.x] = incl - v;
}

__device__ __forceinline__ unsigned edge_base(int e) {
    return g_off[e] + g_bsum[e >> 9];        // SCAN_BLK == 512
}

// ---------------------------------------------------------------------------
// perm: CSR scatter of packed {src, dst, cos(theta)} (one STG.128 per triplet)
// ---------------------------------------------------------------------------
__global__ void k_perm(const int* __restrict__ tsrc, const int* __restrict__ tdst, int T) {
    int t = blockIdx.x * blockDim.x + threadIdx.x;
    if (t >= T) return;
    int s = tsrc[t], d = tdst[t];
    unsigned pos = edge_base(d) + atomicAdd(&g_cursor[d], 1u);
    float4 rs = __ldg(&g_rnorm4[s]);
    float4 rd = __ldg(&g_rnorm4[d]);
    float cth = rs.x * rd.x + rs.y * rd.y + rs.z * rd.z;
    cth = fminf(fmaxf(cth, -1.0f + 1e-6f), 1.0f - 1e-6f);
    g_pack[pos] = make_int4(s, d, __float_as_int(cth), 0);
}

// ---------------------------------------------------------------------------
// pass1 (R8-proven structure): exp(logit) per CSR slot.
//  - xij[src] staged to smem (coalesced, odd stride 65 -> conflict-free LDS)
//  - xij[dst] loaded inside the compute loop (16 independent LDG.128, warp-
//    broadcast + L1 hits; latency overlaps the MUFU chain)
//  - Chebyshev 3-term recurrence (1 FMA/ch; 4 updates per 4-channel group)
//  - silu with 4-way batched reciprocal using FAST intrinsics:
//    1 MUFU.EX2 per channel + 1 MUFU.RCP per 4 channels
//  - dual logit accumulators (halves the serial FMA chain)
//  No softmax max subtraction (|logit| << 88; alpha identical — R4-R11).
// ---------------------------------------------------------------------------
__global__ void __launch_bounds__(TPB1)
k_pass1(const float* __restrict__ xij, const float* __restrict__ attn, int T) {
    __shared__ float sx[TPB1 * RS];
    __shared__ float sat[CCH];
    int tid = threadIdx.x;
    int base = blockIdx.x * TPB1;
    if (tid < CCH) sat[tid] = attn[tid];

    int lane = tid & 31, w = tid >> 5;
    for (int j = w; j < TPB1; j += TPB1 / 32) {
        int t = base + j;
        if (t < T) {
            int s = __ldg(&g_pack[t].x);   // warp-uniform -> broadcast
            float2 v = __ldg((const float2*)(xij + (size_t)s * CCH) + lane);
            sx[j * RS + 2 * lane]     = v.x;
            sx[j * RS + 2 * lane + 1] = v.y;
        }
    }
    __syncthreads();

    int t = base + tid;
    if (t >= T) return;

    int4 p = __ldg(&g_pack[t]);
    int d = p.y;
    float cth = __int_as_float(p.z);
    float c2 = 2.0f * cth;
    float zp = cth, zc = 1.0f;   // T_{-1}, T_0

    const float4* xd = (const float4*)(xij + (size_t)d * CCH);
    const float* row = &sx[tid * RS];
    float a0 = 0.0f, a1 = 0.0f;

#pragma unroll
    for (int k = 0; k < CCH / 4; k++) {
        float4 Dv = __ldg(xd + k);
        // Chebyshev T_{4k}..T_{4k+3}; 4 updates/group, hands T_{4k+4} onward
        float v0 = zc + row[4 * k + 0] + Dv.x;
        float z1 = fmaf(c2, zc, -zp);
        float v1 = z1 + row[4 * k + 1] + Dv.y;
        float z2 = fmaf(c2, z1, -zc);
        float v2 = z2 + row[4 * k + 2] + Dv.z;
        float z3 = fmaf(c2, z2, -z1);
        float v3 = z3 + row[4 * k + 3] + Dv.w;
        float z4 = fmaf(c2, z3, -z2);
        zp = z3; zc = z4;

        // silu via 4-way batched reciprocal: 4 MUFU.EX2 + 1 MUFU.RCP
        float A = 1.0f + __expf(-v0);
        float B = 1.0f + __expf(-v1);
        float C = 1.0f + __expf(-v2);
        float D = 1.0f + __expf(-v3);
        float AB = A * B, CD = C * D;
        float rall = __fdividef(1.0f, AB * CD);
        float rAB = rall * CD, rCD = rall * AB;

        a0 = fmaf(v0 * (B * rAB), sat[4 * k + 0], a0);
        a1 = fmaf(v1 * (A * rAB), sat[4 * k + 1], a1);
        a0 = fmaf(v2 * (D * rCD), sat[4 * k + 2], a0);
        a1 = fmaf(v3 * (C * rCD), sat[4 * k + 3], a1);
    }
    g_se[t] = make_int2(p.x, __float_as_int(__expf(a0 + a1)));  // STG.64
}

// ---------------------------------------------------------------------------
// edge: warp-per-edge aggregate: ft = (sum ex*x[src]) / sum ex.
// Lane owns channels {2*lane, 2*lane+1}. Restores g_cnt/g_cursor to zero.
// ---------------------------------------------------------------------------
__global__ void __launch_bounds__(256)
k_edge(const float* __restrict__ xij, float* __restrict__ ft, int E) {
    int warp = (blockIdx.x * blockDim.x + threadIdx.x) >> 5;
    int lane = threadIdx.x & 31;
    if (warp >= E) return;

    int base = (int)edge_base(warp);
    int deg  = (int)g_cnt[warp];
    if (lane == 0) { g_cnt[warp] = 0u; g_cursor[warp] = 0u; }

    float ax = 0.0f, ay = 0.0f, den = 0.0f;

    int i = 0;
    for (; i + 4 <= deg; i += 4) {
        int2 p0 = __ldg(&g_se[base + i + 0]);
        int2 p1 = __ldg(&g_se[base + i + 1]);
        int2 p2 = __ldg(&g_se[base + i + 2]);
        int2 p3 = __ldg(&g_se[base + i + 3]);
        float2 v0 = __ldg((const float2*)(xij + (size_t)p0.x * CCH) + lane);
        float2 v1 = __ldg((const float2*)(xij + (size_t)p1.x * CCH) + lane);
        float2 v2 = __ldg((const float2*)(xij + (size_t)p2.x * CCH) + lane);
        float2 v3 = __ldg((const float2*)(xij + (size_t)p3.x * CCH) + lane);
        float e0 = __int_as_float(p0.y), e1 = __int_as_float(p1.y);
        float e2 = __int_as_float(p2.y), e3 = __int_as_float(p3.y);
        den += (e0 + e1) + (e2 + e3);
        ax = fmaf(e0, v0.x, ax); ay = fmaf(e0, v0.y, ay);
        ax = fmaf(e1, v1.x, ax); ay = fmaf(e1, v1.y, ay);
        ax = fmaf(e2, v2.x, ax); ay = fmaf(e2, v2.y, ay);
        ax = fmaf(e3, v3.x, ax); ay = fmaf(e3, v3.y, ay);
    }
    for (; i < deg; i++) {
        int2 p0 = __ldg(&g_se[base + i]);
        float2 v0 = __ldg((const float2*)(xij + (size_t)p0.x * CCH) + lane);
        float e0 = __int_as_float(p0.y);
        den += e0;
        ax = fmaf(e0, v0.x, ax); ay = fmaf(e0, v0.y, ay);
    }

    float inv = (deg > 0) ? __fdividef(1.0f, den) : 0.0f;
    *((float2*)(ft + (size_t)warp * CCH) + lane) = make_float2(ax * inv, ay * inv);
}

// ---------------------------------------------------------------------------
extern "C" void kernel_launch(void* const* d_in, const int* in_sizes, int n_in,
                              void* d_out, int out_size) {
    const float* xij  = (const float*)d_in[0];
    const float* r    = (const float*)d_in[1];
    const float* attn = (const float*)d_in[2];
    const int*   tsrc = (const int*)d_in[3];
    const int*   tdst = (const int*)d_in[4];
    float* ft = (float*)d_out;

    int E = in_sizes[1] / 3;
    int T = in_sizes[3];
    int nsb = (E + SCAN_BLK - 1) / SCAN_BLK;
    int nmx = (T > E) ? T : E;

    k_prep_count<<<(nmx + 255) / 256, 256>>>(r, tdst, E, T);
    k_scan1<<<nsb, SCAN_BLK>>>(E);
    k_scan2<<<1,   SCAN_BLK>>>(nsb);
    k_perm <<<(T + 255) / 256, 256>>>(tsrc, tdst, T);
    k_pass1<<<(T + TPB1 - 1) / TPB1, TPB1>>>(xij, attn, T);
    k_edge <<<(E * 32 + 255) / 256, 256>>>(xij, ft, E);
}